// round 11
// baseline (speedup 1.0000x reference)
#include <cuda_runtime.h>

// SSIM loss — register/shuffle-resident separable box filter, v7.
// v3 kernel body (fastest validated) + persistent z-blocks: grid z halved,
// each block processes 2 batches serially. Shrinks the global L2 reuse
// window (old-row re-reads 11 iterations later) from ~113MB to ~56MB so
// retiring-row loads hit L2 instead of DRAM.

#define IMG_H 1024
#define IMG_W 1024
#define BATCH 32
#define PADR 5
#define OUT_W 240          // output cols per warp strip (lanes 1..30 x 8)
#define NSTRIPS 5          // ceil(1024/240); strip 4 partial (64 cols)
#define YCHUNK 64
#define NYCH 16
#define ZUNITS 2           // batches per persistent block
#define ZGRID (BATCH / ZUNITS)   // 16

typedef unsigned long long u64;

static __device__ double g_accum;   // zero-initialized at module load

// finalize also re-zeroes the accumulator -> only 2 launches per replay
__global__ void finalize_kernel(float* out) {
    *out = (float)(1.0 - g_accum * (1.0 / 33554432.0));  // mean over 32*1024*1024
    g_accum = 0.0;
}

__device__ __forceinline__ u64 pk(float lo, float hi) {
    u64 r; asm("mov.b64 %0,{%1,%2};" : "=l"(r) : "f"(lo), "f"(hi)); return r;
}
__device__ __forceinline__ void upk(u64 v, float& lo, float& hi) {
    asm("mov.b64 {%0,%1},%2;" : "=f"(lo), "=f"(hi) : "l"(v));
}
__device__ __forceinline__ u64 f2add(u64 a, u64 b) {
    u64 r; asm("add.rn.f32x2 %0,%1,%2;" : "=l"(r) : "l"(a), "l"(b)); return r;
}
__device__ __forceinline__ u64 f2mul(u64 a, u64 b) {
    u64 r; asm("mul.rn.f32x2 %0,%1,%2;" : "=l"(r) : "l"(a), "l"(b)); return r;
}
__device__ __forceinline__ u64 f2fma(u64 a, u64 b, u64 c) {
    u64 r; asm("fma.rn.f32x2 %0,%1,%2,%3;" : "=l"(r) : "l"(a), "l"(b), "l"(c)); return r;
}

#define NEG1PK 0xBF800000BF800000ULL   // (-1.0f, -1.0f)

__global__ __launch_bounds__(32)
void ssim_kernel(const float* __restrict__ img1, const float* __restrict__ img2) {
    const int lane  = threadIdx.x;
    const int strip = blockIdx.x;
    const int y0    = blockIdx.y * YCHUNK;

    const int j = strip * OUT_W - 8 + lane * 8;   // first owned column (may be OOB)
    const unsigned FULL = 0xffffffffu;
    const bool prod = (lane >= 1) && (lane <= 30);

    // rescaled SSIM constants: multiply num & den by 121^4 (exact ratio)
    const u64 K1P  = pk(1.4641f, 1.4641f);     // C1 * 121^2
    const u64 K2P  = pk(13.1769f, 13.1769f);   // C2 * 121^2
    const u64 TWO  = pk(2.f, 2.f);
    const u64 NTWO = pk(-2.f, -2.f);
    const u64 C242 = pk(242.f, 242.f);
    const u64 C121 = pk(121.f, 121.f);

    double acc = 0.0;

    #pragma unroll 1
    for (int zu = 0; zu < ZUNITS; zu++) {
        const int b = blockIdx.z + zu * ZGRID;
        const size_t ib = (size_t)b * (IMG_H * IMG_W);
        const float* __restrict__ p1 = img1 + ib;
        const float* __restrict__ p2 = img2 + ib;

        // packed column sums: quantities {a, b, a^2, b^2, ab} x 4 col-pairs
        u64 cs[5][4];
        #pragma unroll
        for (int q = 0; q < 5; q++)
            #pragma unroll
            for (int p = 0; p < 4; p++) cs[q][p] = 0ull;

        auto ldp = [&](int row, int c, float4& a, float4& bb) {
            if (row >= 0 && row < IMG_H && c >= 0 && c + 3 < IMG_W) {
                const size_t idx = (size_t)row * IMG_W + c;
                a  = *(const float4*)(p1 + idx);
                bb = *(const float4*)(p2 + idx);
            } else {
                a  = make_float4(0.f, 0.f, 0.f, 0.f);
                bb = make_float4(0.f, 0.f, 0.f, 0.f);
            }
        };

        auto upd_pair = [&](int pi, u64 an, u64 bn, u64 ao, u64 bo) {
            u64 aon = f2mul(ao, (u64)NEG1PK);
            u64 bon = f2mul(bo, (u64)NEG1PK);
            cs[0][pi] = f2add(f2add(cs[0][pi], an), aon);
            cs[1][pi] = f2add(f2add(cs[1][pi], bn), bon);
            cs[2][pi] = f2fma(aon, ao, f2fma(an, an, cs[2][pi]));
            cs[3][pi] = f2fma(bon, bo, f2fma(bn, bn, cs[3][pi]));
            cs[4][pi] = f2fma(aon, bo, f2fma(an, bn, cs[4][pi]));
        };

        auto update = [&](int rn, int ro) {
            #pragma unroll
            for (int g = 0; g < 2; g++) {
                float4 anv, bnv, aov, bov;
                ldp(rn, j + 4 * g, anv, bnv);
                ldp(ro, j + 4 * g, aov, bov);
                upd_pair(2 * g + 0, pk(anv.x, anv.y), pk(bnv.x, bnv.y),
                                    pk(aov.x, aov.y), pk(bov.x, bov.y));
                upd_pair(2 * g + 1, pk(anv.z, anv.w), pk(bnv.z, bnv.w),
                                    pk(aov.z, aov.w), pk(bov.z, bov.w));
            }
        };

        // ---- prologue: rows y0-5 .. y0+4 (old row OOB -> zero) ----
        #pragma unroll 1
        for (int r = 0; r < 10; r++) update(y0 - PADR + r, -10000);

        // ---- main loop ----
        #pragma unroll 1
        for (int i = 0; i < YCHUNK; i++) {
            const int oy = y0 + i;
            // window grows 10->11 at i==0 (row oy-6 was never added)
            update(oy + PADR, (i == 0) ? -10000 : (oy - PADR - 1));

            // horizontal 11-col window sums W[q][0..7] for outputs at cols j..j+7
            float W[5][8];
            #pragma unroll
            for (int q = 0; q < 5; q++) {
                float c0, c1, c2, c3, c4, c5, c6, c7;
                upk(cs[q][0], c0, c1); upk(cs[q][1], c2, c3);
                upk(cs[q][2], c4, c5); upk(cs[q][3], c6, c7);

                u64  Lp2 = __shfl_up_sync(FULL, cs[q][2], 1);   // cols j-4, j-3
                u64  Lp3 = __shfl_up_sync(FULL, cs[q][3], 1);   // cols j-2, j-1
                float l5 = __shfl_up_sync(FULL, c3, 1);         // col  j-5
                u64  Rp0 = __shfl_down_sync(FULL, cs[q][0], 1); // cols j+8, j+9
                u64  Rp1 = __shfl_down_sync(FULL, cs[q][1], 1); // cols j+10, j+11
                float r12 = __shfl_down_sync(FULL, c4, 1);      // col  j+12

                float L1v, L2v, L3v, L4v, R0v, R1v, R2v, R3v;
                upk(Lp2, L1v, L2v);
                upk(Lp3, L3v, L4v);
                upk(Rp0, R0v, R1v);
                upk(Rp1, R2v, R3v);

                u64 t = f2add(f2add(Lp2, Lp3), f2add(cs[q][0], cs[q][1]));
                float t0, t1; upk(t, t0, t1);
                const float base8 = t0 + t1;            // cols j-4 .. j+3

                W[q][0] = base8 + l5 + c4 + c5;         // j-5 .. j+5
                W[q][1] = W[q][0] - l5  + c6;
                W[q][2] = W[q][1] - L1v + c7;
                W[q][3] = W[q][2] - L2v + R0v;
                W[q][4] = W[q][3] - L3v + R1v;
                W[q][5] = W[q][4] - L4v + R2v;
                W[q][6] = W[q][5] - c0  + R3v;
                W[q][7] = W[q][6] - c1  + r12;
            }

            float rsum = 0.f;
            #pragma unroll
            for (int k = 0; k < 4; k++) {
                u64 s1  = pk(W[0][2*k], W[0][2*k+1]);
                u64 s2  = pk(W[1][2*k], W[1][2*k+1]);
                u64 s11 = pk(W[2][2*k], W[2][2*k+1]);
                u64 s22 = pk(W[3][2*k], W[3][2*k+1]);
                u64 s12 = pk(W[4][2*k], W[4][2*k+1]);

                u64 P   = f2mul(s1, s2);
                u64 A   = f2fma(P, TWO, K1P);                       // 2*S1S2 + K1
                u64 B   = f2fma(s12, C242, f2fma(P, NTWO, K2P));    // 242*S12 - 2*S1S2 + K2
                u64 num = f2mul(A, B);
                u64 Q   = f2fma(s2, s2, f2mul(s1, s1));             // S1^2 + S2^2
                u64 Cc  = f2add(Q, K1P);
                u64 D   = f2fma(f2add(s11, s22), C121,
                                f2fma(Q, (u64)NEG1PK, K2P));        // 121*(S11+S22) - Q + K2
                u64 den = f2mul(Cc, D);

                float n0, n1, d0, d1;
                upk(num, n0, n1); upk(den, d0, d1);
                if (prod) {
                    const int col = j + 2 * k;
                    if (col < IMG_W)     rsum += __fdividef(n0, d0);
                    if (col + 1 < IMG_W) rsum += __fdividef(n1, d1);
                }
            }
            acc += (double)rsum;
        }
    }

    // ---- warp reduce + one atomic per warp ----
    #pragma unroll
    for (int off = 16; off > 0; off >>= 1)
        acc += __shfl_down_sync(FULL, acc, off);
    if (lane == 0) atomicAdd(&g_accum, acc);
}

extern "C" void kernel_launch(void* const* d_in, const int* in_sizes, int n_in,
                              void* d_out, int out_size) {
    const float* img1 = (const float*)d_in[0];
    const float* img2 = (const float*)d_in[1];
    (void)in_sizes; (void)n_in; (void)out_size;

    // g_accum: zero at module load; finalize_kernel re-zeroes it every call.
    dim3 grid(NSTRIPS, NYCH, ZGRID);   // (5, 16, 16) = 1280 persistent blocks
    ssim_kernel<<<grid, 32>>>(img1, img2);
    finalize_kernel<<<1, 1>>>((float*)d_out);
}

// round 12
// speedup vs baseline: 1.5987x; 1.5987x over previous
#include <cuda_runtime.h>

// SSIM loss — register/shuffle-resident separable box filter, v8.
// v3 body and grid (fastest validated: 2560 single-warp blocks, one wave);
// change: maintain merged S11+S22 column sums -> 4 quantities instead of 5
// (SSIM only consumes the sum), cutting shuffle/FMA work and registers.

#define IMG_H 1024
#define IMG_W 1024
#define BATCH 32
#define PADR 5
#define OUT_W 240          // output cols per warp strip (lanes 1..30 x 8)
#define NSTRIPS 5          // ceil(1024/240); strip 4 partial (64 cols)
#define YCHUNK 64
#define NYCH 16

typedef unsigned long long u64;

static __device__ double g_accum;   // zero-initialized at module load

// finalize also re-zeroes the accumulator -> only 2 launches per replay
__global__ void finalize_kernel(float* out) {
    *out = (float)(1.0 - g_accum * (1.0 / 33554432.0));  // mean over 32*1024*1024
    g_accum = 0.0;
}

__device__ __forceinline__ u64 pk(float lo, float hi) {
    u64 r; asm("mov.b64 %0,{%1,%2};" : "=l"(r) : "f"(lo), "f"(hi)); return r;
}
__device__ __forceinline__ void upk(u64 v, float& lo, float& hi) {
    asm("mov.b64 {%0,%1},%2;" : "=f"(lo), "=f"(hi) : "l"(v));
}
__device__ __forceinline__ u64 f2add(u64 a, u64 b) {
    u64 r; asm("add.rn.f32x2 %0,%1,%2;" : "=l"(r) : "l"(a), "l"(b)); return r;
}
__device__ __forceinline__ u64 f2mul(u64 a, u64 b) {
    u64 r; asm("mul.rn.f32x2 %0,%1,%2;" : "=l"(r) : "l"(a), "l"(b)); return r;
}
__device__ __forceinline__ u64 f2fma(u64 a, u64 b, u64 c) {
    u64 r; asm("fma.rn.f32x2 %0,%1,%2,%3;" : "=l"(r) : "l"(a), "l"(b), "l"(c)); return r;
}

#define NEG1PK 0xBF800000BF800000ULL   // (-1.0f, -1.0f)

__global__ __launch_bounds__(32)
void ssim_kernel(const float* __restrict__ img1, const float* __restrict__ img2) {
    const int lane  = threadIdx.x;
    const int strip = blockIdx.x;
    const int y0    = blockIdx.y * YCHUNK;
    const size_t ib = (size_t)blockIdx.z * (IMG_H * IMG_W);
    const float* __restrict__ p1 = img1 + ib;
    const float* __restrict__ p2 = img2 + ib;

    const int j = strip * OUT_W - 8 + lane * 8;   // first owned column (may be OOB)
    const unsigned FULL = 0xffffffffu;
    const bool prod = (lane >= 1) && (lane <= 30);

    // packed column sums over current 11-row window:
    // quantities {S1=a, S2=b, S1122=a^2+b^2, S12=ab} x 4 col-pairs
    u64 cs[4][4];
    #pragma unroll
    for (int q = 0; q < 4; q++)
        #pragma unroll
        for (int p = 0; p < 4; p++) cs[q][p] = 0ull;

    auto ldp = [&](int row, int c, float4& a, float4& b) {
        if (row >= 0 && row < IMG_H && c >= 0 && c + 3 < IMG_W) {
            const size_t idx = (size_t)row * IMG_W + c;
            a = *(const float4*)(p1 + idx);
            b = *(const float4*)(p2 + idx);
        } else {
            a = make_float4(0.f, 0.f, 0.f, 0.f);
            b = make_float4(0.f, 0.f, 0.f, 0.f);
        }
    };

    auto upd_pair = [&](int pi, u64 an, u64 bn, u64 ao, u64 bo) {
        u64 aon = f2mul(ao, (u64)NEG1PK);
        u64 bon = f2mul(bo, (u64)NEG1PK);
        cs[0][pi] = f2add(f2add(cs[0][pi], an), aon);
        cs[1][pi] = f2add(f2add(cs[1][pi], bn), bon);
        // merged: d(a^2+b^2) = an*an + bn*bn - ao*ao - bo*bo
        cs[2][pi] = f2fma(aon, ao, f2fma(bon, bo,
                    f2fma(an, an, f2fma(bn, bn, cs[2][pi]))));
        cs[3][pi] = f2fma(aon, bo, f2fma(an, bn, cs[3][pi]));
    };

    // loads issued as a front batch, consumed immediately (short live ranges)
    auto update = [&](int rn, int ro) {
        #pragma unroll
        for (int g = 0; g < 2; g++) {
            float4 anv, bnv, aov, bov;
            ldp(rn, j + 4 * g, anv, bnv);
            ldp(ro, j + 4 * g, aov, bov);
            upd_pair(2 * g + 0, pk(anv.x, anv.y), pk(bnv.x, bnv.y),
                                pk(aov.x, aov.y), pk(bov.x, bov.y));
            upd_pair(2 * g + 1, pk(anv.z, anv.w), pk(bnv.z, bnv.w),
                                pk(aov.z, aov.w), pk(bov.z, bov.w));
        }
    };

    // rescaled SSIM constants: multiply num & den by 121^4 (exact ratio)
    const u64 K1P  = pk(1.4641f, 1.4641f);     // C1 * 121^2
    const u64 K2P  = pk(13.1769f, 13.1769f);   // C2 * 121^2
    const u64 TWO  = pk(2.f, 2.f);
    const u64 NTWO = pk(-2.f, -2.f);
    const u64 C242 = pk(242.f, 242.f);
    const u64 C121 = pk(121.f, 121.f);

    // ---- prologue: rows y0-5 .. y0+4 (old row OOB -> zero contribution) ----
    #pragma unroll 1
    for (int r = 0; r < 10; r++) update(y0 - PADR + r, -10000);

    double acc = 0.0;

    // ---- main loop ----
    #pragma unroll 1
    for (int i = 0; i < YCHUNK; i++) {
        const int oy = y0 + i;
        // slide: add row oy+5, drop row oy-6 (OOB at i==0: window grows 10->11)
        update(oy + PADR, (i == 0) ? -10000 : (oy - PADR - 1));

        // horizontal 11-col window sums W[q][0..7] for outputs at cols j..j+7
        float W[4][8];
        #pragma unroll
        for (int q = 0; q < 4; q++) {
            float c0, c1, c2, c3, c4, c5, c6, c7;
            upk(cs[q][0], c0, c1); upk(cs[q][1], c2, c3);
            upk(cs[q][2], c4, c5); upk(cs[q][3], c6, c7);

            u64  Lp2 = __shfl_up_sync(FULL, cs[q][2], 1);   // cols j-4, j-3
            u64  Lp3 = __shfl_up_sync(FULL, cs[q][3], 1);   // cols j-2, j-1
            float l5 = __shfl_up_sync(FULL, c3, 1);         // col  j-5
            u64  Rp0 = __shfl_down_sync(FULL, cs[q][0], 1); // cols j+8, j+9
            u64  Rp1 = __shfl_down_sync(FULL, cs[q][1], 1); // cols j+10, j+11
            float r12 = __shfl_down_sync(FULL, c4, 1);      // col  j+12

            float L1v, L2v, L3v, L4v, R0v, R1v, R2v, R3v;
            upk(Lp2, L1v, L2v);
            upk(Lp3, L3v, L4v);
            upk(Rp0, R0v, R1v);
            upk(Rp1, R2v, R3v);

            u64 t = f2add(f2add(Lp2, Lp3), f2add(cs[q][0], cs[q][1]));
            float t0, t1; upk(t, t0, t1);
            const float base8 = t0 + t1;            // cols j-4 .. j+3

            W[q][0] = base8 + l5 + c4 + c5;         // j-5 .. j+5
            W[q][1] = W[q][0] - l5  + c6;
            W[q][2] = W[q][1] - L1v + c7;
            W[q][3] = W[q][2] - L2v + R0v;
            W[q][4] = W[q][3] - L3v + R1v;
            W[q][5] = W[q][4] - L4v + R2v;
            W[q][6] = W[q][5] - c0  + R3v;
            W[q][7] = W[q][6] - c1  + r12;
        }

        float rsum = 0.f;
        #pragma unroll
        for (int k = 0; k < 4; k++) {
            u64 s1    = pk(W[0][2*k], W[0][2*k+1]);
            u64 s2    = pk(W[1][2*k], W[1][2*k+1]);
            u64 s1122 = pk(W[2][2*k], W[2][2*k+1]);
            u64 s12   = pk(W[3][2*k], W[3][2*k+1]);

            u64 P   = f2mul(s1, s2);
            u64 A   = f2fma(P, TWO, K1P);                       // 2*S1S2 + K1
            u64 B   = f2fma(s12, C242, f2fma(P, NTWO, K2P));    // 242*S12 - 2*S1S2 + K2
            u64 num = f2mul(A, B);
            u64 Q   = f2fma(s2, s2, f2mul(s1, s1));             // S1^2 + S2^2
            u64 Cc  = f2add(Q, K1P);
            u64 D   = f2fma(s1122, C121,
                            f2fma(Q, (u64)NEG1PK, K2P));        // 121*(S11+S22) - Q + K2
            u64 den = f2mul(Cc, D);

            float n0, n1, d0, d1;
            upk(num, n0, n1); upk(den, d0, d1);
            if (prod) {
                const int col = j + 2 * k;
                if (col < IMG_W)     rsum += __fdividef(n0, d0);
                if (col + 1 < IMG_W) rsum += __fdividef(n1, d1);
            }
        }
        acc += (double)rsum;
    }

    // ---- warp reduce + one atomic per warp ----
    #pragma unroll
    for (int off = 16; off > 0; off >>= 1)
        acc += __shfl_down_sync(FULL, acc, off);
    if (lane == 0) atomicAdd(&g_accum, acc);
}

extern "C" void kernel_launch(void* const* d_in, const int* in_sizes, int n_in,
                              void* d_out, int out_size) {
    const float* img1 = (const float*)d_in[0];
    const float* img2 = (const float*)d_in[1];
    (void)in_sizes; (void)n_in; (void)out_size;

    // g_accum: zeroed at module load; finalize_kernel re-zeroes after reading.
    dim3 grid(NSTRIPS, NYCH, BATCH);   // (5, 16, 32) = 2560 single-warp blocks
    ssim_kernel<<<grid, 32>>>(img1, img2);
    finalize_kernel<<<1, 1>>>((float*)d_out);
}

// round 13
// speedup vs baseline: 1.6993x; 1.0629x over previous
#include <cuda_runtime.h>

// SSIM loss — register/shuffle-resident separable box filter, v9.
// v8 body (4 merged quantities, fastest validated 117.9us) + 1-deep prefetch
// of the incoming row ONLY (the DRAM-latency load). The retiring row is
// re-read at use: it was fetched 11 iterations ago by this same warp and
// reliably hits L2 (~250cyc), so it doesn't need prefetch registers.

#define IMG_H 1024
#define IMG_W 1024
#define BATCH 32
#define PADR 5
#define OUT_W 240          // output cols per warp strip (lanes 1..30 x 8)
#define NSTRIPS 5          // ceil(1024/240); strip 4 partial (64 cols)
#define YCHUNK 64
#define NYCH 16

typedef unsigned long long u64;

static __device__ double g_accum;   // zero-initialized at module load

// finalize also re-zeroes the accumulator -> only 2 launches per replay
__global__ void finalize_kernel(float* out) {
    *out = (float)(1.0 - g_accum * (1.0 / 33554432.0));  // mean over 32*1024*1024
    g_accum = 0.0;
}

__device__ __forceinline__ u64 pk(float lo, float hi) {
    u64 r; asm("mov.b64 %0,{%1,%2};" : "=l"(r) : "f"(lo), "f"(hi)); return r;
}
__device__ __forceinline__ void upk(u64 v, float& lo, float& hi) {
    asm("mov.b64 {%0,%1},%2;" : "=f"(lo), "=f"(hi) : "l"(v));
}
__device__ __forceinline__ u64 f2add(u64 a, u64 b) {
    u64 r; asm("add.rn.f32x2 %0,%1,%2;" : "=l"(r) : "l"(a), "l"(b)); return r;
}
__device__ __forceinline__ u64 f2mul(u64 a, u64 b) {
    u64 r; asm("mul.rn.f32x2 %0,%1,%2;" : "=l"(r) : "l"(a), "l"(b)); return r;
}
__device__ __forceinline__ u64 f2fma(u64 a, u64 b, u64 c) {
    u64 r; asm("fma.rn.f32x2 %0,%1,%2,%3;" : "=l"(r) : "l"(a), "l"(b), "l"(c)); return r;
}

#define NEG1PK 0xBF800000BF800000ULL   // (-1.0f, -1.0f)

__global__ __launch_bounds__(32)
void ssim_kernel(const float* __restrict__ img1, const float* __restrict__ img2) {
    const int lane  = threadIdx.x;
    const int strip = blockIdx.x;
    const int y0    = blockIdx.y * YCHUNK;
    const size_t ib = (size_t)blockIdx.z * (IMG_H * IMG_W);
    const float* __restrict__ p1 = img1 + ib;
    const float* __restrict__ p2 = img2 + ib;

    const int j = strip * OUT_W - 8 + lane * 8;   // first owned column (may be OOB)
    const unsigned FULL = 0xffffffffu;
    const bool prod = (lane >= 1) && (lane <= 30);

    // packed column sums over current 11-row window:
    // quantities {S1=a, S2=b, S1122=a^2+b^2, S12=ab} x 4 col-pairs
    u64 cs[4][4];
    #pragma unroll
    for (int q = 0; q < 4; q++)
        #pragma unroll
        for (int p = 0; p < 4; p++) cs[q][p] = 0ull;

    auto ldp = [&](int row, int c, float4& a, float4& b) {
        if (row >= 0 && row < IMG_H && c >= 0 && c + 3 < IMG_W) {
            const size_t idx = (size_t)row * IMG_W + c;
            a = *(const float4*)(p1 + idx);
            b = *(const float4*)(p2 + idx);
        } else {
            a = make_float4(0.f, 0.f, 0.f, 0.f);
            b = make_float4(0.f, 0.f, 0.f, 0.f);
        }
    };

    auto upd_pair = [&](int pi, u64 an, u64 bn, u64 ao, u64 bo) {
        u64 aon = f2mul(ao, (u64)NEG1PK);
        u64 bon = f2mul(bo, (u64)NEG1PK);
        cs[0][pi] = f2add(f2add(cs[0][pi], an), aon);
        cs[1][pi] = f2add(f2add(cs[1][pi], bn), bon);
        // merged: d(a^2+b^2) = an*an + bn*bn - ao*ao - bo*bo
        cs[2][pi] = f2fma(aon, ao, f2fma(bon, bo,
                    f2fma(an, an, f2fma(bn, bn, cs[2][pi]))));
        cs[3][pi] = f2fma(aon, bo, f2fma(an, bn, cs[3][pi]));
    };

    // prefetched incoming-row registers (consumed by the next update)
    float4 Na0, Nb0, Na1, Nb1;

    // update using prefetched new row; retiring row loaded here at use
    // (L2-resident: this warp read it 11 iterations ago)
    auto update_consume = [&](int ro) {
        float4 Oa0, Ob0, Oa1, Ob1;
        ldp(ro, j,     Oa0, Ob0);
        ldp(ro, j + 4, Oa1, Ob1);
        upd_pair(0, pk(Na0.x, Na0.y), pk(Nb0.x, Nb0.y), pk(Oa0.x, Oa0.y), pk(Ob0.x, Ob0.y));
        upd_pair(1, pk(Na0.z, Na0.w), pk(Nb0.z, Nb0.w), pk(Oa0.z, Oa0.w), pk(Ob0.z, Ob0.w));
        upd_pair(2, pk(Na1.x, Na1.y), pk(Nb1.x, Nb1.y), pk(Oa1.x, Oa1.y), pk(Ob1.x, Ob1.y));
        upd_pair(3, pk(Na1.z, Na1.w), pk(Nb1.z, Nb1.w), pk(Oa1.z, Oa1.w), pk(Ob1.z, Ob1.w));
    };

    // rescaled SSIM constants: multiply num & den by 121^4 (exact ratio)
    const u64 K1P  = pk(1.4641f, 1.4641f);     // C1 * 121^2
    const u64 K2P  = pk(13.1769f, 13.1769f);   // C2 * 121^2
    const u64 TWO  = pk(2.f, 2.f);
    const u64 NTWO = pk(-2.f, -2.f);
    const u64 C242 = pk(242.f, 242.f);
    const u64 C121 = pk(121.f, 121.f);

    // ---- prologue: rows y0-5 .. y0+4 accumulate (retiring row OOB -> zero) ----
    ldp(y0 - PADR, j,     Na0, Nb0);
    ldp(y0 - PADR, j + 4, Na1, Nb1);
    #pragma unroll 1
    for (int r = 0; r < 10; r++) {
        update_consume(-10000);
        const int nr = y0 - PADR + 1 + r;      // r==9 loads y0+5: main's first new row
        ldp(nr, j,     Na0, Nb0);
        ldp(nr, j + 4, Na1, Nb1);
    }

    double acc = 0.0;

    // ---- main loop ----
    #pragma unroll 1
    for (int i = 0; i < YCHUNK; i++) {
        const int oy = y0 + i;
        // consume prefetched row oy+5; drop row oy-6 (OOB at i==0: window grows 10->11)
        update_consume((i == 0) ? -10000 : (oy - PADR - 1));

        // prefetch next iteration's incoming row (oy+6); OOB-safe past the image
        ldp(oy + PADR + 1, j,     Na0, Nb0);
        ldp(oy + PADR + 1, j + 4, Na1, Nb1);

        // horizontal 11-col window sums W[q][0..7] for outputs at cols j..j+7
        float W[4][8];
        #pragma unroll
        for (int q = 0; q < 4; q++) {
            float c0, c1, c2, c3, c4, c5, c6, c7;
            upk(cs[q][0], c0, c1); upk(cs[q][1], c2, c3);
            upk(cs[q][2], c4, c5); upk(cs[q][3], c6, c7);

            u64  Lp2 = __shfl_up_sync(FULL, cs[q][2], 1);   // cols j-4, j-3
            u64  Lp3 = __shfl_up_sync(FULL, cs[q][3], 1);   // cols j-2, j-1
            float l5 = __shfl_up_sync(FULL, c3, 1);         // col  j-5
            u64  Rp0 = __shfl_down_sync(FULL, cs[q][0], 1); // cols j+8, j+9
            u64  Rp1 = __shfl_down_sync(FULL, cs[q][1], 1); // cols j+10, j+11
            float r12 = __shfl_down_sync(FULL, c4, 1);      // col  j+12

            float L1v, L2v, L3v, L4v, R0v, R1v, R2v, R3v;
            upk(Lp2, L1v, L2v);
            upk(Lp3, L3v, L4v);
            upk(Rp0, R0v, R1v);
            upk(Rp1, R2v, R3v);

            u64 t = f2add(f2add(Lp2, Lp3), f2add(cs[q][0], cs[q][1]));
            float t0, t1; upk(t, t0, t1);
            const float base8 = t0 + t1;            // cols j-4 .. j+3

            W[q][0] = base8 + l5 + c4 + c5;         // j-5 .. j+5
            W[q][1] = W[q][0] - l5  + c6;
            W[q][2] = W[q][1] - L1v + c7;
            W[q][3] = W[q][2] - L2v + R0v;
            W[q][4] = W[q][3] - L3v + R1v;
            W[q][5] = W[q][4] - L4v + R2v;
            W[q][6] = W[q][5] - c0  + R3v;
            W[q][7] = W[q][6] - c1  + r12;
        }

        float rsum = 0.f;
        #pragma unroll
        for (int k = 0; k < 4; k++) {
            u64 s1    = pk(W[0][2*k], W[0][2*k+1]);
            u64 s2    = pk(W[1][2*k], W[1][2*k+1]);
            u64 s1122 = pk(W[2][2*k], W[2][2*k+1]);
            u64 s12   = pk(W[3][2*k], W[3][2*k+1]);

            u64 P   = f2mul(s1, s2);
            u64 A   = f2fma(P, TWO, K1P);                       // 2*S1S2 + K1
            u64 B   = f2fma(s12, C242, f2fma(P, NTWO, K2P));    // 242*S12 - 2*S1S2 + K2
            u64 num = f2mul(A, B);
            u64 Q   = f2fma(s2, s2, f2mul(s1, s1));             // S1^2 + S2^2
            u64 Cc  = f2add(Q, K1P);
            u64 D   = f2fma(s1122, C121,
                            f2fma(Q, (u64)NEG1PK, K2P));        // 121*(S11+S22) - Q + K2
            u64 den = f2mul(Cc, D);

            float n0, n1, d0, d1;
            upk(num, n0, n1); upk(den, d0, d1);
            if (prod) {
                const int col = j + 2 * k;
                if (col < IMG_W)     rsum += __fdividef(n0, d0);
                if (col + 1 < IMG_W) rsum += __fdividef(n1, d1);
            }
        }
        acc += (double)rsum;
    }

    // ---- warp reduce + one atomic per warp ----
    #pragma unroll
    for (int off = 16; off > 0; off >>= 1)
        acc += __shfl_down_sync(FULL, acc, off);
    if (lane == 0) atomicAdd(&g_accum, acc);
}

extern "C" void kernel_launch(void* const* d_in, const int* in_sizes, int n_in,
                              void* d_out, int out_size) {
    const float* img1 = (const float*)d_in[0];
    const float* img2 = (const float*)d_in[1];
    (void)in_sizes; (void)n_in; (void)out_size;

    // g_accum: zeroed at module load; finalize_kernel re-zeroes after reading.
    dim3 grid(NSTRIPS, NYCH, BATCH);   // (5, 16, 32) = 2560 single-warp blocks
    ssim_kernel<<<grid, 32>>>(img1, img2);
    finalize_kernel<<<1, 1>>>((float*)d_out);
}

// round 15
// speedup vs baseline: 1.7358x; 1.0215x over previous
#include <cuda_runtime.h>

// SSIM loss — register/shuffle-resident separable box filter, v10 (resubmit;
// round-14 bench was an infra failure, container never ran the kernel).
// v9 (110.9us: 4 merged quantities + new-row-only prefetch) with the
// delta-form vertical update, tested in isolation:
//   d(a^2+b^2) = (an-ao)(an+ao) + (bn-bo)(bn+bo)
//   d(ab)      = (an-ao)*bn + ao*(bn-bo)
// 10 f2 ops/pair vs 12; operands born packed from LDG.128 quads.

#define IMG_H 1024
#define IMG_W 1024
#define BATCH 32
#define PADR 5
#define OUT_W 240          // output cols per warp strip (lanes 1..30 x 8)
#define NSTRIPS 5          // ceil(1024/240); strip 4 partial (64 cols)
#define YCHUNK 64
#define NYCH 16

typedef unsigned long long u64;

static __device__ double g_accum;   // zero-initialized at module load

// finalize also re-zeroes the accumulator -> only 2 launches per replay
__global__ void finalize_kernel(float* out) {
    *out = (float)(1.0 - g_accum * (1.0 / 33554432.0));  // mean over 32*1024*1024
    g_accum = 0.0;
}

__device__ __forceinline__ u64 pk(float lo, float hi) {
    u64 r; asm("mov.b64 %0,{%1,%2};" : "=l"(r) : "f"(lo), "f"(hi)); return r;
}
__device__ __forceinline__ void upk(u64 v, float& lo, float& hi) {
    asm("mov.b64 {%0,%1},%2;" : "=f"(lo), "=f"(hi) : "l"(v));
}
__device__ __forceinline__ u64 f2add(u64 a, u64 b) {
    u64 r; asm("add.rn.f32x2 %0,%1,%2;" : "=l"(r) : "l"(a), "l"(b)); return r;
}
__device__ __forceinline__ u64 f2mul(u64 a, u64 b) {
    u64 r; asm("mul.rn.f32x2 %0,%1,%2;" : "=l"(r) : "l"(a), "l"(b)); return r;
}
__device__ __forceinline__ u64 f2fma(u64 a, u64 b, u64 c) {
    u64 r; asm("fma.rn.f32x2 %0,%1,%2,%3;" : "=l"(r) : "l"(a), "l"(b), "l"(c)); return r;
}

#define NEG1PK 0xBF800000BF800000ULL   // (-1.0f, -1.0f)
__device__ __forceinline__ u64 f2sub(u64 a, u64 b) { return f2fma(b, (u64)NEG1PK, a); }

__global__ __launch_bounds__(32)
void ssim_kernel(const float* __restrict__ img1, const float* __restrict__ img2) {
    const int lane  = threadIdx.x;
    const int strip = blockIdx.x;
    const int y0    = blockIdx.y * YCHUNK;
    const size_t ib = (size_t)blockIdx.z * (IMG_H * IMG_W);
    const float* __restrict__ p1 = img1 + ib;
    const float* __restrict__ p2 = img2 + ib;

    const int j = strip * OUT_W - 8 + lane * 8;   // first owned column (may be OOB)
    const unsigned FULL = 0xffffffffu;
    const bool prod = (lane >= 1) && (lane <= 30);

    // packed column sums over current 11-row window:
    // quantities {S1=a, S2=b, S1122=a^2+b^2, S12=ab} x 4 col-pairs
    u64 cs[4][4];
    #pragma unroll
    for (int q = 0; q < 4; q++)
        #pragma unroll
        for (int p = 0; p < 4; p++) cs[q][p] = 0ull;

    auto ldp = [&](int row, int c, float4& a, float4& b) {
        if (row >= 0 && row < IMG_H && c >= 0 && c + 3 < IMG_W) {
            const size_t idx = (size_t)row * IMG_W + c;
            a = *(const float4*)(p1 + idx);
            b = *(const float4*)(p2 + idx);
        } else {
            a = make_float4(0.f, 0.f, 0.f, 0.f);
            b = make_float4(0.f, 0.f, 0.f, 0.f);
        }
    };

    // Delta-form update (exact algebra, no negation constants):
    auto upd_pair = [&](int pi, u64 an, u64 bn, u64 ao, u64 bo) {
        u64 da = f2sub(an, ao);
        u64 db = f2sub(bn, bo);
        u64 sa = f2add(an, ao);
        u64 sb = f2add(bn, bo);
        cs[0][pi] = f2add(cs[0][pi], da);
        cs[1][pi] = f2add(cs[1][pi], db);
        cs[2][pi] = f2fma(db, sb, f2fma(da, sa, cs[2][pi]));
        cs[3][pi] = f2fma(da, bn, f2fma(ao, db, cs[3][pi]));
    };

    // prefetched incoming-row registers (consumed by the next update)
    float4 Na0, Nb0, Na1, Nb1;

    // update using prefetched new row; retiring row loaded here at use
    // (L2-resident: this warp read it 11 iterations ago)
    auto update_consume = [&](int ro) {
        float4 Oa0, Ob0, Oa1, Ob1;
        ldp(ro, j,     Oa0, Ob0);
        ldp(ro, j + 4, Oa1, Ob1);
        upd_pair(0, pk(Na0.x, Na0.y), pk(Nb0.x, Nb0.y), pk(Oa0.x, Oa0.y), pk(Ob0.x, Ob0.y));
        upd_pair(1, pk(Na0.z, Na0.w), pk(Nb0.z, Nb0.w), pk(Oa0.z, Oa0.w), pk(Ob0.z, Ob0.w));
        upd_pair(2, pk(Na1.x, Na1.y), pk(Nb1.x, Nb1.y), pk(Oa1.x, Oa1.y), pk(Ob1.x, Ob1.y));
        upd_pair(3, pk(Na1.z, Na1.w), pk(Nb1.z, Nb1.w), pk(Oa1.z, Oa1.w), pk(Ob1.z, Ob1.w));
    };

    // rescaled SSIM constants: multiply num & den by 121^4 (exact ratio)
    const u64 K1P  = pk(1.4641f, 1.4641f);     // C1 * 121^2
    const u64 K2P  = pk(13.1769f, 13.1769f);   // C2 * 121^2
    const u64 TWO  = pk(2.f, 2.f);
    const u64 NTWO = pk(-2.f, -2.f);
    const u64 C242 = pk(242.f, 242.f);
    const u64 C121 = pk(121.f, 121.f);

    // ---- prologue: rows y0-5 .. y0+4 accumulate (retiring row OOB -> zero) ----
    ldp(y0 - PADR, j,     Na0, Nb0);
    ldp(y0 - PADR, j + 4, Na1, Nb1);
    #pragma unroll 1
    for (int r = 0; r < 10; r++) {
        update_consume(-10000);
        const int nr = y0 - PADR + 1 + r;      // r==9 loads y0+5: main's first new row
        ldp(nr, j,     Na0, Nb0);
        ldp(nr, j + 4, Na1, Nb1);
    }

    double acc = 0.0;

    // ---- main loop ----
    #pragma unroll 1
    for (int i = 0; i < YCHUNK; i++) {
        const int oy = y0 + i;
        // consume prefetched row oy+5; drop row oy-6 (OOB at i==0: window grows 10->11)
        update_consume((i == 0) ? -10000 : (oy - PADR - 1));

        // prefetch next iteration's incoming row (oy+6); OOB-safe past the image
        ldp(oy + PADR + 1, j,     Na0, Nb0);
        ldp(oy + PADR + 1, j + 4, Na1, Nb1);

        // horizontal 11-col window sums W[q][0..7] for outputs at cols j..j+7
        float W[4][8];
        #pragma unroll
        for (int q = 0; q < 4; q++) {
            float c0, c1, c2, c3, c4, c5, c6, c7;
            upk(cs[q][0], c0, c1); upk(cs[q][1], c2, c3);
            upk(cs[q][2], c4, c5); upk(cs[q][3], c6, c7);

            u64  Lp2 = __shfl_up_sync(FULL, cs[q][2], 1);   // cols j-4, j-3
            u64  Lp3 = __shfl_up_sync(FULL, cs[q][3], 1);   // cols j-2, j-1
            float l5 = __shfl_up_sync(FULL, c3, 1);         // col  j-5
            u64  Rp0 = __shfl_down_sync(FULL, cs[q][0], 1); // cols j+8, j+9
            u64  Rp1 = __shfl_down_sync(FULL, cs[q][1], 1); // cols j+10, j+11
            float r12 = __shfl_down_sync(FULL, c4, 1);      // col  j+12

            float L1v, L2v, L3v, L4v, R0v, R1v, R2v, R3v;
            upk(Lp2, L1v, L2v);
            upk(Lp3, L3v, L4v);
            upk(Rp0, R0v, R1v);
            upk(Rp1, R2v, R3v);

            u64 t = f2add(f2add(Lp2, Lp3), f2add(cs[q][0], cs[q][1]));
            float t0, t1; upk(t, t0, t1);
            const float base8 = t0 + t1;            // cols j-4 .. j+3

            W[q][0] = base8 + l5 + c4 + c5;         // j-5 .. j+5
            W[q][1] = W[q][0] - l5  + c6;
            W[q][2] = W[q][1] - L1v + c7;
            W[q][3] = W[q][2] - L2v + R0v;
            W[q][4] = W[q][3] - L3v + R1v;
            W[q][5] = W[q][4] - L4v + R2v;
            W[q][6] = W[q][5] - c0  + R3v;
            W[q][7] = W[q][6] - c1  + r12;
        }

        float rsum = 0.f;
        #pragma unroll
        for (int k = 0; k < 4; k++) {
            u64 s1    = pk(W[0][2*k], W[0][2*k+1]);
            u64 s2    = pk(W[1][2*k], W[1][2*k+1]);
            u64 s1122 = pk(W[2][2*k], W[2][2*k+1]);
            u64 s12   = pk(W[3][2*k], W[3][2*k+1]);

            u64 P   = f2mul(s1, s2);
            u64 A   = f2fma(P, TWO, K1P);                       // 2*S1S2 + K1
            u64 B   = f2fma(s12, C242, f2fma(P, NTWO, K2P));    // 242*S12 - 2*S1S2 + K2
            u64 num = f2mul(A, B);
            u64 Q   = f2fma(s2, s2, f2mul(s1, s1));             // S1^2 + S2^2
            u64 Cc  = f2add(Q, K1P);
            u64 D   = f2fma(s1122, C121,
                            f2fma(Q, (u64)NEG1PK, K2P));        // 121*(S11+S22) - Q + K2
            u64 den = f2mul(Cc, D);

            float n0, n1, d0, d1;
            upk(num, n0, n1); upk(den, d0, d1);
            if (prod) {
                const int col = j + 2 * k;
                if (col < IMG_W)     rsum += __fdividef(n0, d0);
                if (col + 1 < IMG_W) rsum += __fdividef(n1, d1);
            }
        }
        acc += (double)rsum;
    }

    // ---- warp reduce + one atomic per warp ----
    #pragma unroll
    for (int off = 16; off > 0; off >>= 1)
        acc += __shfl_down_sync(FULL, acc, off);
    if (lane == 0) atomicAdd(&g_accum, acc);
}

extern "C" void kernel_launch(void* const* d_in, const int* in_sizes, int n_in,
                              void* d_out, int out_size) {
    const float* img1 = (const float*)d_in[0];
    const float* img2 = (const float*)d_in[1];
    (void)in_sizes; (void)n_in; (void)out_size;

    // g_accum: zeroed at module load; finalize_kernel re-zeroes after reading.
    dim3 grid(NSTRIPS, NYCH, BATCH);   // (5, 16, 32) = 2560 single-warp blocks
    ssim_kernel<<<grid, 32>>>(img1, img2);
    finalize_kernel<<<1, 1>>>((float*)d_out);
}

// round 17
// speedup vs baseline: 1.7364x; 1.0003x over previous
#include <cuda_runtime.h>

// SSIM loss — register/shuffle-resident separable box filter, v11 (resubmit;
// round-16 bench was an infra failure — container never ran the kernel).
// v10 (108.5us) + __launch_bounds__(32, 18): force the register budget to
// <=112/thread so all 2560 single-warp blocks fit the chip in ONE wave
// (148 SMs x 18 = 2664 >= 2560), eliminating the ~15% straggler tail that
// the ~130-reg allocation (15 blocks/SM residency) was causing.

#define IMG_H 1024
#define IMG_W 1024
#define BATCH 32
#define PADR 5
#define OUT_W 240          // output cols per warp strip (lanes 1..30 x 8)
#define NSTRIPS 5          // ceil(1024/240); strip 4 partial (64 cols)
#define YCHUNK 64
#define NYCH 16

typedef unsigned long long u64;

static __device__ double g_accum;   // zero-initialized at module load

// finalize also re-zeroes the accumulator -> only 2 launches per replay
__global__ void finalize_kernel(float* out) {
    *out = (float)(1.0 - g_accum * (1.0 / 33554432.0));  // mean over 32*1024*1024
    g_accum = 0.0;
}

__device__ __forceinline__ u64 pk(float lo, float hi) {
    u64 r; asm("mov.b64 %0,{%1,%2};" : "=l"(r) : "f"(lo), "f"(hi)); return r;
}
__device__ __forceinline__ void upk(u64 v, float& lo, float& hi) {
    asm("mov.b64 {%0,%1},%2;" : "=f"(lo), "=f"(hi) : "l"(v));
}
__device__ __forceinline__ u64 f2add(u64 a, u64 b) {
    u64 r; asm("add.rn.f32x2 %0,%1,%2;" : "=l"(r) : "l"(a), "l"(b)); return r;
}
__device__ __forceinline__ u64 f2mul(u64 a, u64 b) {
    u64 r; asm("mul.rn.f32x2 %0,%1,%2;" : "=l"(r) : "l"(a), "l"(b)); return r;
}
__device__ __forceinline__ u64 f2fma(u64 a, u64 b, u64 c) {
    u64 r; asm("fma.rn.f32x2 %0,%1,%2,%3;" : "=l"(r) : "l"(a), "l"(b), "l"(c)); return r;
}

#define NEG1PK 0xBF800000BF800000ULL   // (-1.0f, -1.0f)
__device__ __forceinline__ u64 f2sub(u64 a, u64 b) { return f2fma(b, (u64)NEG1PK, a); }

__global__ __launch_bounds__(32, 18)
void ssim_kernel(const float* __restrict__ img1, const float* __restrict__ img2) {
    const int lane  = threadIdx.x;
    const int strip = blockIdx.x;
    const int y0    = blockIdx.y * YCHUNK;
    const size_t ib = (size_t)blockIdx.z * (IMG_H * IMG_W);
    const float* __restrict__ p1 = img1 + ib;
    const float* __restrict__ p2 = img2 + ib;

    const int j = strip * OUT_W - 8 + lane * 8;   // first owned column (may be OOB)
    const unsigned FULL = 0xffffffffu;
    const bool prod = (lane >= 1) && (lane <= 30);

    // packed column sums over current 11-row window:
    // quantities {S1=a, S2=b, S1122=a^2+b^2, S12=ab} x 4 col-pairs
    u64 cs[4][4];
    #pragma unroll
    for (int q = 0; q < 4; q++)
        #pragma unroll
        for (int p = 0; p < 4; p++) cs[q][p] = 0ull;

    auto ldp = [&](int row, int c, float4& a, float4& b) {
        if (row >= 0 && row < IMG_H && c >= 0 && c + 3 < IMG_W) {
            const size_t idx = (size_t)row * IMG_W + c;
            a = *(const float4*)(p1 + idx);
            b = *(const float4*)(p2 + idx);
        } else {
            a = make_float4(0.f, 0.f, 0.f, 0.f);
            b = make_float4(0.f, 0.f, 0.f, 0.f);
        }
    };

    // Delta-form update (exact algebra, no negation constants):
    auto upd_pair = [&](int pi, u64 an, u64 bn, u64 ao, u64 bo) {
        u64 da = f2sub(an, ao);
        u64 db = f2sub(bn, bo);
        u64 sa = f2add(an, ao);
        u64 sb = f2add(bn, bo);
        cs[0][pi] = f2add(cs[0][pi], da);
        cs[1][pi] = f2add(cs[1][pi], db);
        cs[2][pi] = f2fma(db, sb, f2fma(da, sa, cs[2][pi]));
        cs[3][pi] = f2fma(da, bn, f2fma(ao, db, cs[3][pi]));
    };

    // prefetched incoming-row registers (consumed by the next update)
    float4 Na0, Nb0, Na1, Nb1;

    // update using prefetched new row; retiring row loaded here at use
    // (L2-resident: this warp read it 11 iterations ago)
    auto update_consume = [&](int ro) {
        float4 Oa0, Ob0, Oa1, Ob1;
        ldp(ro, j,     Oa0, Ob0);
        ldp(ro, j + 4, Oa1, Ob1);
        upd_pair(0, pk(Na0.x, Na0.y), pk(Nb0.x, Nb0.y), pk(Oa0.x, Oa0.y), pk(Ob0.x, Ob0.y));
        upd_pair(1, pk(Na0.z, Na0.w), pk(Nb0.z, Nb0.w), pk(Oa0.z, Oa0.w), pk(Ob0.z, Ob0.w));
        upd_pair(2, pk(Na1.x, Na1.y), pk(Nb1.x, Nb1.y), pk(Oa1.x, Oa1.y), pk(Ob1.x, Ob1.y));
        upd_pair(3, pk(Na1.z, Na1.w), pk(Nb1.z, Nb1.w), pk(Oa1.z, Oa1.w), pk(Ob1.z, Ob1.w));
    };

    // rescaled SSIM constants: multiply num & den by 121^4 (exact ratio)
    const u64 K1P  = pk(1.4641f, 1.4641f);     // C1 * 121^2
    const u64 K2P  = pk(13.1769f, 13.1769f);   // C2 * 121^2
    const u64 TWO  = pk(2.f, 2.f);
    const u64 NTWO = pk(-2.f, -2.f);
    const u64 C242 = pk(242.f, 242.f);
    const u64 C121 = pk(121.f, 121.f);

    // ---- prologue: rows y0-5 .. y0+4 accumulate (retiring row OOB -> zero) ----
    ldp(y0 - PADR, j,     Na0, Nb0);
    ldp(y0 - PADR, j + 4, Na1, Nb1);
    #pragma unroll 1
    for (int r = 0; r < 10; r++) {
        update_consume(-10000);
        const int nr = y0 - PADR + 1 + r;      // r==9 loads y0+5: main's first new row
        ldp(nr, j,     Na0, Nb0);
        ldp(nr, j + 4, Na1, Nb1);
    }

    double acc = 0.0;

    // ---- main loop ----
    #pragma unroll 1
    for (int i = 0; i < YCHUNK; i++) {
        const int oy = y0 + i;
        // consume prefetched row oy+5; drop row oy-6 (OOB at i==0: window grows 10->11)
        update_consume((i == 0) ? -10000 : (oy - PADR - 1));

        // prefetch next iteration's incoming row (oy+6); OOB-safe past the image
        ldp(oy + PADR + 1, j,     Na0, Nb0);
        ldp(oy + PADR + 1, j + 4, Na1, Nb1);

        // horizontal 11-col window sums W[q][0..7] for outputs at cols j..j+7
        float W[4][8];
        #pragma unroll
        for (int q = 0; q < 4; q++) {
            float c0, c1, c2, c3, c4, c5, c6, c7;
            upk(cs[q][0], c0, c1); upk(cs[q][1], c2, c3);
            upk(cs[q][2], c4, c5); upk(cs[q][3], c6, c7);

            u64  Lp2 = __shfl_up_sync(FULL, cs[q][2], 1);   // cols j-4, j-3
            u64  Lp3 = __shfl_up_sync(FULL, cs[q][3], 1);   // cols j-2, j-1
            float l5 = __shfl_up_sync(FULL, c3, 1);         // col  j-5
            u64  Rp0 = __shfl_down_sync(FULL, cs[q][0], 1); // cols j+8, j+9
            u64  Rp1 = __shfl_down_sync(FULL, cs[q][1], 1); // cols j+10, j+11
            float r12 = __shfl_down_sync(FULL, c4, 1);      // col  j+12

            float L1v, L2v, L3v, L4v, R0v, R1v, R2v, R3v;
            upk(Lp2, L1v, L2v);
            upk(Lp3, L3v, L4v);
            upk(Rp0, R0v, R1v);
            upk(Rp1, R2v, R3v);

            u64 t = f2add(f2add(Lp2, Lp3), f2add(cs[q][0], cs[q][1]));
            float t0, t1; upk(t, t0, t1);
            const float base8 = t0 + t1;            // cols j-4 .. j+3

            W[q][0] = base8 + l5 + c4 + c5;         // j-5 .. j+5
            W[q][1] = W[q][0] - l5  + c6;
            W[q][2] = W[q][1] - L1v + c7;
            W[q][3] = W[q][2] - L2v + R0v;
            W[q][4] = W[q][3] - L3v + R1v;
            W[q][5] = W[q][4] - L4v + R2v;
            W[q][6] = W[q][5] - c0  + R3v;
            W[q][7] = W[q][6] - c1  + r12;
        }

        float rsum = 0.f;
        #pragma unroll
        for (int k = 0; k < 4; k++) {
            u64 s1    = pk(W[0][2*k], W[0][2*k+1]);
            u64 s2    = pk(W[1][2*k], W[1][2*k+1]);
            u64 s1122 = pk(W[2][2*k], W[2][2*k+1]);
            u64 s12   = pk(W[3][2*k], W[3][2*k+1]);

            u64 P   = f2mul(s1, s2);
            u64 A   = f2fma(P, TWO, K1P);                       // 2*S1S2 + K1
            u64 B   = f2fma(s12, C242, f2fma(P, NTWO, K2P));    // 242*S12 - 2*S1S2 + K2
            u64 num = f2mul(A, B);
            u64 Q   = f2fma(s2, s2, f2mul(s1, s1));             // S1^2 + S2^2
            u64 Cc  = f2add(Q, K1P);
            u64 D   = f2fma(s1122, C121,
                            f2fma(Q, (u64)NEG1PK, K2P));        // 121*(S11+S22) - Q + K2
            u64 den = f2mul(Cc, D);

            float n0, n1, d0, d1;
            upk(num, n0, n1); upk(den, d0, d1);
            if (prod) {
                const int col = j + 2 * k;
                if (col < IMG_W)     rsum += __fdividef(n0, d0);
                if (col + 1 < IMG_W) rsum += __fdividef(n1, d1);
            }
        }
        acc += (double)rsum;
    }

    // ---- warp reduce + one atomic per warp ----
    #pragma unroll
    for (int off = 16; off > 0; off >>= 1)
        acc += __shfl_down_sync(FULL, acc, off);
    if (lane == 0) atomicAdd(&g_accum, acc);
}

extern "C" void kernel_launch(void* const* d_in, const int* in_sizes, int n_in,
                              void* d_out, int out_size) {
    const float* img1 = (const float*)d_in[0];
    const float* img2 = (const float*)d_in[1];
    (void)in_sizes; (void)n_in; (void)out_size;

    // g_accum: zeroed at module load; finalize_kernel re-zeroes after reading.
    dim3 grid(NSTRIPS, NYCH, BATCH);   // (5, 16, 32) = 2560 single-warp blocks
    ssim_kernel<<<grid, 32>>>(img1, img2);
    finalize_kernel<<<1, 1>>>((float*)d_out);
}